// round 14
// baseline (speedup 1.0000x reference)
#include <cuda_runtime.h>
#include <cuda_fp16.h>
#include <cstdint>

#define E_TOTAL  1000000
#define NN       100000
#define HDIM     128

// P = emb @ [W1_top | W1_bot] (+b1 folded into cols 0..511), fp16 : [NN][1024]
__device__ __half g_Ph[(size_t)NN * 1024];
// W1 transposed fp16 : [1024 n][128 k]
__device__ __half g_W1T[(size_t)1024 * 128];
// W2 transposed fp16 : [128 n][512 k]
__device__ __half g_W2T[(size_t)128 * 512];

__device__ __forceinline__ void mma_f16(float* d, const uint32_t* a, const uint32_t* b) {
    asm volatile(
        "mma.sync.aligned.m16n8k16.row.col.f32.f16.f16.f32 "
        "{%0,%1,%2,%3}, {%4,%5,%6,%7}, {%8,%9}, {%0,%1,%2,%3};\n"
        : "+f"(d[0]), "+f"(d[1]), "+f"(d[2]), "+f"(d[3])
        : "r"(a[0]), "r"(a[1]), "r"(a[2]), "r"(a[3]),
          "r"(b[0]), "r"(b[1]));
}
// f16-accumulate: d = 2 regs holding 4 halfs (rows lr / lr+8, cols n,n+1)
__device__ __forceinline__ void mma_f16h(uint32_t* d, const uint32_t* a, const uint32_t* b) {
    asm volatile(
        "mma.sync.aligned.m16n8k16.row.col.f16.f16.f16.f16 "
        "{%0,%1}, {%2,%3,%4,%5}, {%6,%7}, {%0,%1};\n"
        : "+r"(d[0]), "+r"(d[1])
        : "r"(a[0]), "r"(a[1]), "r"(a[2]), "r"(a[3]),
          "r"(b[0]), "r"(b[1]));
}
__device__ __forceinline__ uint32_t f2h2(float lo, float hi) {
    __half2 p = __floats2half2_rn(lo, hi);
    return *reinterpret_cast<uint32_t*>(&p);
}
__device__ __forceinline__ float2 h2f(uint32_t w) {
    __half2 h = *reinterpret_cast<__half2*>(&w);
    return __half22float2(h);
}
__device__ __forceinline__ uint32_t addrelu(uint32_t a, uint32_t b) {
    __half2 s = __hmax2(__hadd2(*reinterpret_cast<__half2*>(&a),
                                *reinterpret_cast<__half2*>(&b)),
                        __float2half2_rn(0.f));
    return *reinterpret_cast<uint32_t*>(&s);
}
__device__ __forceinline__ void cp16(uint32_t s, const void* g) {
    asm volatile("cp.async.cg.shared.global [%0], [%1], 16;\n" :: "r"(s), "l"(g));
}
__device__ __forceinline__ void cp_commit() {
    asm volatile("cp.async.commit_group;\n");
}
template <int N>
__device__ __forceinline__ void cp_wait() {
    asm volatile("cp.async.wait_group %0;\n" :: "n"(N));
}
__device__ __forceinline__ uint32_t smem_u32(const void* p) {
    uint32_t a;
    asm("{ .reg .u64 t; cvta.to.shared.u64 t, %1; cvt.u32.u64 %0, t; }" : "=r"(a) : "l"(p));
    return a;
}

// ============================================================================
// Kernel 0: prep — W1 -> g_W1T fp16 [1024][128]; W2 -> g_W2T fp16 [128][512]
// ============================================================================
__global__ __launch_bounds__(256) void prep_kernel(
    const float* __restrict__ W1, const float* __restrict__ W2)
{
    int bid = blockIdx.x;
    int tid = threadIdx.x;
    if (bid < 512) {
        int idx = bid * 256 + tid;
        int k = idx >> 10;
        int n = idx & 1023;
        float v = (n < 512) ? W1[(size_t)k * 512 + n]
                            : W1[(size_t)(128 + k) * 512 + (n - 512)];
        g_W1T[(size_t)n * 128 + k] = __float2half_rn(v);
    } else {
        int idx = (bid - 512) * 256 + tid;
        int k = idx >> 7;
        int n = idx & 127;
        g_W2T[(size_t)n * 512 + k] = __float2half_rn(W2[(size_t)k * 128 + n]);
    }
}

// ============================================================================
// Kernel 1: P = emb @ Wcat (+ b1 on cols<512) -> fp16. Tile 128x128, K=128.
// ============================================================================
#define PC_STR 68
#define PC_SMEM (2 * 128 * PC_STR * 4)

__global__ __launch_bounds__(256, 2) void precompute_kernel(
    const float* __restrict__ emb, const float* __restrict__ b1)
{
    extern __shared__ char smem_raw[];
    uint32_t* As = (uint32_t*)smem_raw;
    uint32_t* Ws = As + 128 * PC_STR;

    const int tid  = threadIdx.x;
    const int warp = tid >> 5;
    const int lane = tid & 31;
    const int q    = lane & 3;
    const int lr   = lane >> 2;
    const int wm   = warp >> 2;
    const int wn   = warp & 3;
    const int row0 = blockIdx.x * 128;
    const int nblk = blockIdx.y;

    const int rj = tid & 15;
    const int rr = tid >> 4;

    #pragma unroll
    for (int pass = 0; pass < 8; pass++) {
        int r = pass * 16 + rr;
        int node = row0 + r;
        if (node >= NN) node = NN - 1;
        const float4* src = (const float4*)(emb + (size_t)node * HDIM + rj * 8);
        float4 a0 = src[0];
        float4 a1 = src[1];
        uint4 h;
        h.x = f2h2(a0.x, a0.y);
        h.y = f2h2(a0.z, a0.w);
        h.z = f2h2(a1.x, a1.y);
        h.w = f2h2(a1.z, a1.w);
        *(uint4*)(As + r * PC_STR + rj * 4) = h;

        uint4 v = *(const uint4*)(g_W1T + (size_t)(nblk * 128 + r) * 128 + rj * 8);
        *(uint4*)(Ws + r * PC_STR + rj * 4) = v;
    }
    __syncthreads();

    float acc[4][4][4];
    #pragma unroll
    for (int mt = 0; mt < 4; mt++)
        #pragma unroll
        for (int nt = 0; nt < 4; nt++)
            #pragma unroll
            for (int i = 0; i < 4; i++) acc[mt][nt][i] = 0.f;

    #pragma unroll
    for (int s = 0; s < 8; s++) {
        uint32_t bfr[4][2];
        #pragma unroll
        for (int nt = 0; nt < 4; nt++) {
            const uint32_t* bp = Ws + (wn * 32 + nt * 8 + lr) * PC_STR + q + 8 * s;
            bfr[nt][0] = bp[0];
            bfr[nt][1] = bp[4];
        }
        #pragma unroll
        for (int mt = 0; mt < 4; mt++) {
            const uint32_t* ap = As + (wm * 64 + mt * 16 + lr) * PC_STR + q + 8 * s;
            uint32_t a[4];
            a[0] = ap[0];
            a[1] = ap[8 * PC_STR];
            a[2] = ap[4];
            a[3] = ap[8 * PC_STR + 4];
            #pragma unroll
            for (int nt = 0; nt < 4; nt++)
                mma_f16(acc[mt][nt], a, bfr[nt]);
        }
    }

    const bool bias = (nblk < 4);
    #pragma unroll
    for (int mt = 0; mt < 4; mt++) {
        int n0 = row0 + wm * 64 + mt * 16 + lr;
        #pragma unroll
        for (int nt = 0; nt < 4; nt++) {
            int c = nblk * 128 + wn * 32 + nt * 8 + q * 2;
            float a0 = acc[mt][nt][0], a1 = acc[mt][nt][1];
            float a2 = acc[mt][nt][2], a3 = acc[mt][nt][3];
            if (bias) {
                float u = b1[c], v = b1[c + 1];
                a0 += u; a1 += v; a2 += u; a3 += v;
            }
            if (n0 < NN)
                *(uint32_t*)(g_Ph + (size_t)n0 * 1024 + c) = f2h2(a0, a1);
            if (n0 + 8 < NN)
                *(uint32_t*)(g_Ph + (size_t)(n0 + 8) * 1024 + c) = f2h2(a2, a3);
        }
    }
}

// ============================================================================
// Kernel 2: edge MLP — R6's 609us pipeline (128 threads, 2M x 2N, tile
// 128 e x 128 N, K=512 in 8 chunks of 64, LDG->reg gather 2 ahead, transform
// fused into the single STS, cp.async W2 [R6 plan: 8 x 16B per thread,
// ALL 128 rows], 1 sync/chunk) with:
//   (1) f16 accumulators  -> 64 acc regs (R11-proven accuracy)
//   (2) smem = EXACTLY 73728 B = 9 x 8KB pages -> 3 CTAs/SM (12 warps)
// ============================================================================
#define HS_STR 36                         // uint32 words per 64-half row
#define H1_B   (128 * HS_STR * 4)         // 18432 bytes
#define STG_B  (2 * H1_B)                 // h1 | W2 = 36864
#define EK_SMEM (2 * STG_B)               // 73728 = 9 smem pages exactly

__global__ __launch_bounds__(128, 3) void edge_kernel(
    const int* __restrict__ ei,
    const float* __restrict__ b2, const float* __restrict__ W3,
    const float* __restrict__ b3, float* __restrict__ out)
{
    extern __shared__ char smem_raw[];
    uint32_t* pipe = (uint32_t*)smem_raw;                    // [2][h1|W2]

    const int tid  = threadIdx.x;
    const int warp = tid >> 5;
    const int lane = tid & 31;
    const int q    = lane & 3;
    const int lr   = lane >> 2;
    const int wy   = warp >> 1;          // 0..1 : M group (64 edges)
    const int wx   = warp & 1;           // 0..1 : N group (64 cols)
    const int e0   = blockIdx.x * 128;

    // stage edge indices in pipe region, cache to regs, then reuse region
    {
        int eg = e0 + tid;
        int c = 0, r = 0;
        if (eg < E_TOTAL) { c = ei[eg]; r = ei[E_TOTAL + eg]; }
        ((int*)pipe)[tid]       = c;
        ((int*)pipe)[128 + tid] = r;
    }
    __syncthreads();

    const uint32_t smemBase = smem_u32(pipe);

    // ---- gather plan: 4 threads/edge (32B seg j4), 4 passes of 32 edges ----
    const int j4 = tid & 3;
    const int eT = tid >> 2;              // 0..31
    uint32_t paOff[4], pbOff[4];
    #pragma unroll
    for (int p = 0; p < 4; p++) {
        int e = p * 32 + eT;
        int cN = ((int*)pipe)[e];
        int rN = ((int*)pipe)[128 + e];
        paOff[p] = (uint32_t)cN * 2048u + j4 * 32u;
        pbOff[p] = (uint32_t)rN * 2048u + 1024u + j4 * 32u;
    }
    const uint32_t hD0 = smemBase + (uint32_t)(eT * HS_STR) * 4u + j4 * 32u;
    // per-pass h1 dst: hD0 + p * (32*HS_STR*4) = hD0 + p * 4608
    __syncthreads();    // index reads done before pipe reuse

    // ---- W2 staging plan (R6): 8 threads/row (16B seg), 8 passes x 16 rows --
    const int j8  = tid & 7;
    const int n16 = tid >> 3;             // 0..15
    const uint32_t wOff0 = (uint32_t)n16 * 1024u + j8 * 16u;       // + p*16384
    const uint32_t wD0   = smemBase + (uint32_t)H1_B
                         + (uint32_t)(n16 * HS_STR) * 4u + j8 * 16u; // + p*2304

    const char* gP = (const char*)g_Ph;
    const char* gW = (const char*)g_W2T;

    uint4 rA[2][2], rB[2][2];     // passes 0,1
    uint4 rA2[2][2], rB2[2][2];   // passes 2,3

    // ---- prologue ----
    #pragma unroll
    for (int p = 0; p < 2; p++) {
        rA[p][0] = *(const uint4*)(gP + paOff[p]);
        rA[p][1] = *(const uint4*)(gP + paOff[p] + 16);
        rB[p][0] = *(const uint4*)(gP + pbOff[p]);
        rB[p][1] = *(const uint4*)(gP + pbOff[p] + 16);
        rA2[p][0] = *(const uint4*)(gP + paOff[p + 2]);
        rA2[p][1] = *(const uint4*)(gP + paOff[p + 2] + 16);
        rB2[p][0] = *(const uint4*)(gP + pbOff[p + 2]);
        rB2[p][1] = *(const uint4*)(gP + pbOff[p + 2] + 16);
    }
    #pragma unroll
    for (int p = 0; p < 8; p++) cp16(wD0 + p * 2304u, gW + wOff0 + p * 16384u);
    cp_commit();
    // transform chunk 0 -> h1 buf0
    #pragma unroll
    for (int p = 0; p < 2; p++)
        #pragma unroll
        for (int h = 0; h < 2; h++) {
            uint4 v;
            v.x = addrelu(rA[p][h].x, rB[p][h].x);
            v.y = addrelu(rA[p][h].y, rB[p][h].y);
            v.z = addrelu(rA[p][h].z, rB[p][h].z);
            v.w = addrelu(rA[p][h].w, rB[p][h].w);
            asm volatile("st.shared.v4.b32 [%0], {%1,%2,%3,%4};"
                         :: "r"(hD0 + p * 4608u + h * 16u),
                            "r"(v.x), "r"(v.y), "r"(v.z), "r"(v.w) : "memory");
            uint4 w;
            w.x = addrelu(rA2[p][h].x, rB2[p][h].x);
            w.y = addrelu(rA2[p][h].y, rB2[p][h].y);
            w.z = addrelu(rA2[p][h].z, rB2[p][h].z);
            w.w = addrelu(rA2[p][h].w, rB2[p][h].w);
            asm volatile("st.shared.v4.b32 [%0], {%1,%2,%3,%4};"
                         :: "r"(hD0 + (p + 2) * 4608u + h * 16u),
                            "r"(w.x), "r"(w.y), "r"(w.z), "r"(w.w) : "memory");
        }
    // LDG chunk 1
    #pragma unroll
    for (int p = 0; p < 2; p++) {
        rA[p][0] = *(const uint4*)(gP + paOff[p] + 128);
        rA[p][1] = *(const uint4*)(gP + paOff[p] + 144);
        rB[p][0] = *(const uint4*)(gP + pbOff[p] + 128);
        rB[p][1] = *(const uint4*)(gP + pbOff[p] + 144);
        rA2[p][0] = *(const uint4*)(gP + paOff[p + 2] + 128);
        rA2[p][1] = *(const uint4*)(gP + paOff[p + 2] + 144);
        rB2[p][0] = *(const uint4*)(gP + pbOff[p + 2] + 128);
        rB2[p][1] = *(const uint4*)(gP + pbOff[p + 2] + 144);
    }
    cp_wait<0>();
    __syncthreads();

    uint32_t acc[4][8][2];
    #pragma unroll
    for (int mt = 0; mt < 4; mt++)
        #pragma unroll
        for (int nt = 0; nt < 8; nt++) {
            acc[mt][nt][0] = 0u;
            acc[mt][nt][1] = 0u;
        }

    #pragma unroll 1
    for (int kc = 0; kc < 8; kc++) {
        const uint32_t curB = (uint32_t)(kc & 1) * STG_B;
        if (kc < 7) {
            const uint32_t nb = (uint32_t)((kc + 1) & 1) * STG_B;
            // STS h1(kc+1) from regs (transform folded)
            #pragma unroll
            for (int p = 0; p < 2; p++)
                #pragma unroll
                for (int h = 0; h < 2; h++) {
                    uint4 v;
                    v.x = addrelu(rA[p][h].x, rB[p][h].x);
                    v.y = addrelu(rA[p][h].y, rB[p][h].y);
                    v.z = addrelu(rA[p][h].z, rB[p][h].z);
                    v.w = addrelu(rA[p][h].w, rB[p][h].w);
                    asm volatile("st.shared.v4.b32 [%0], {%1,%2,%3,%4};"
                                 :: "r"(hD0 + p * 4608u + nb + h * 16u),
                                    "r"(v.x), "r"(v.y), "r"(v.z), "r"(v.w) : "memory");
                    uint4 w;
                    w.x = addrelu(rA2[p][h].x, rB2[p][h].x);
                    w.y = addrelu(rA2[p][h].y, rB2[p][h].y);
                    w.z = addrelu(rA2[p][h].z, rB2[p][h].z);
                    w.w = addrelu(rA2[p][h].w, rB2[p][h].w);
                    asm volatile("st.shared.v4.b32 [%0], {%1,%2,%3,%4};"
                                 :: "r"(hD0 + (p + 2) * 4608u + nb + h * 16u),
                                    "r"(w.x), "r"(w.y), "r"(w.z), "r"(w.w) : "memory");
                }
            // cp W2(kc+1) — all 128 rows
            {
                const uint32_t kb = (uint32_t)(kc + 1) * 128u;
                #pragma unroll
                for (int p = 0; p < 8; p++)
                    cp16(wD0 + p * 2304u + nb, gW + wOff0 + p * 16384u + kb);
                cp_commit();
            }
            // LDG P(kc+2) -> regs
            if (kc < 6) {
                const uint32_t kb = (uint32_t)(kc + 2) * 128u;
                #pragma unroll
                for (int p = 0; p < 2; p++) {
                    rA[p][0] = *(const uint4*)(gP + paOff[p] + kb);
                    rA[p][1] = *(const uint4*)(gP + paOff[p] + kb + 16);
                    rB[p][0] = *(const uint4*)(gP + pbOff[p] + kb);
                    rB[p][1] = *(const uint4*)(gP + pbOff[p] + kb + 16);
                    rA2[p][0] = *(const uint4*)(gP + paOff[p + 2] + kb);
                    rA2[p][1] = *(const uint4*)(gP + paOff[p + 2] + kb + 16);
                    rB2[p][0] = *(const uint4*)(gP + pbOff[p + 2] + kb);
                    rB2[p][1] = *(const uint4*)(gP + pbOff[p + 2] + kb + 16);
                }
            }
        }
        // mma(kc)
        const uint32_t* Hs = pipe + (curB >> 2);
        const uint32_t* Ws = Hs + (H1_B >> 2);
        #pragma unroll
        for (int s = 0; s < 4; s++) {
            uint32_t bfr[8][2];
            #pragma unroll
            for (int nt = 0; nt < 8; nt++) {
                const uint32_t* bp = Ws + (wx * 64 + nt * 8 + lr) * HS_STR + q + 8 * s;
                bfr[nt][0] = bp[0];
                bfr[nt][1] = bp[4];
            }
            #pragma unroll
            for (int mt = 0; mt < 4; mt++) {
                int ro = (wy * 64 + mt * 16 + lr) * HS_STR + q + 8 * s;
                uint32_t a[4];
                a[0] = Hs[ro];
                a[1] = Hs[ro + 8 * HS_STR];
                a[2] = Hs[ro + 4];
                a[3] = Hs[ro + 8 * HS_STR + 4];
                #pragma unroll
                for (int nt = 0; nt < 8; nt++)
                    mma_f16h(acc[mt][nt], a, bfr[nt]);
            }
        }
        if (kc < 7) {
            cp_wait<0>();
            __syncthreads();
        }
    }
    __syncthreads();

    // ---- epilogue: unpack f16 acc, relu(+b2 via LDG), dot W3, reduce ----
    float* partS = (float*)pipe;          // overlay (all mma reads done)
    #pragma unroll
    for (int mt = 0; mt < 4; mt++) {
        float p0 = 0.f, p1 = 0.f;
        #pragma unroll
        for (int nt = 0; nt < 8; nt++) {
            int n = wx * 64 + nt * 8 + q * 2;
            float2 w3v = *(const float2*)(W3 + n);
            float2 b2v = *(const float2*)(b2 + n);
            float2 lo = h2f(acc[mt][nt][0]);   // row lr   : cols n, n+1
            float2 hi = h2f(acc[mt][nt][1]);   // row lr+8 : cols n, n+1
            p0 += fmaxf(lo.x + b2v.x, 0.f) * w3v.x + fmaxf(lo.y + b2v.y, 0.f) * w3v.y;
            p1 += fmaxf(hi.x + b2v.x, 0.f) * w3v.x + fmaxf(hi.y + b2v.y, 0.f) * w3v.y;
        }
        p0 += __shfl_xor_sync(0xffffffffu, p0, 1);
        p0 += __shfl_xor_sync(0xffffffffu, p0, 2);
        p1 += __shfl_xor_sync(0xffffffffu, p1, 1);
        p1 += __shfl_xor_sync(0xffffffffu, p1, 2);
        if (q == 0) {
            int rl = wy * 64 + mt * 16 + lr;
            partS[wx * 128 + rl]     = p0;
            partS[wx * 128 + rl + 8] = p1;
        }
    }
    __syncthreads();
    {
        float s = partS[tid] + partS[128 + tid] + b3[0];
        int eg = e0 + tid;
        if (eg < E_TOTAL) out[eg] = 1.f / (1.f + expf(-s));
    }
}

// ============================================================================
extern "C" void kernel_launch(void* const* d_in, const int* in_sizes, int n_in,
                              void* d_out, int out_size)
{
    const float* emb = (const float*)d_in[0];
    const int*   ei  = (const int*)d_in[1];
    const float* W1  = (const float*)d_in[2];
    const float* b1  = (const float*)d_in[3];
    const float* W2  = (const float*)d_in[4];
    const float* b2  = (const float*)d_in[5];
    const float* W3  = (const float*)d_in[6];
    const float* b3  = (const float*)d_in[7];
    float* out = (float*)d_out;

    cudaFuncSetAttribute(precompute_kernel,
                         cudaFuncAttributeMaxDynamicSharedMemorySize, PC_SMEM);
    cudaFuncSetAttribute(edge_kernel,
                         cudaFuncAttributeMaxDynamicSharedMemorySize, EK_SMEM);
    cudaFuncSetAttribute(edge_kernel,
                         cudaFuncAttributePreferredSharedMemoryCarveout, 100);

    prep_kernel<<<768, 256>>>(W1, W2);
    precompute_kernel<<<dim3(782, 8), 256, PC_SMEM>>>(emb, b1);
    edge_kernel<<<7813, 128, EK_SMEM>>>(ei, b2, W3, b3, out);
}

// round 15
// speedup vs baseline: 1.3023x; 1.3023x over previous
#include <cuda_runtime.h>
#include <cuda_fp16.h>
#include <cstdint>

#define E_TOTAL  1000000
#define NN       100000
#define HDIM     128

// P = emb @ [W1_top | W1_bot] (+b1 folded into cols 0..511), fp16 : [NN][1024]
__device__ __half g_Ph[(size_t)NN * 1024];
// W1 transposed fp16 : [1024 n][128 k]
__device__ __half g_W1T[(size_t)1024 * 128];
// W2 transposed fp16 : [128 n][512 k]
__device__ __half g_W2T[(size_t)128 * 512];

__device__ __forceinline__ void mma_f16(float* d, const uint32_t* a, const uint32_t* b) {
    asm volatile(
        "mma.sync.aligned.m16n8k16.row.col.f32.f16.f16.f32 "
        "{%0,%1,%2,%3}, {%4,%5,%6,%7}, {%8,%9}, {%0,%1,%2,%3};\n"
        : "+f"(d[0]), "+f"(d[1]), "+f"(d[2]), "+f"(d[3])
        : "r"(a[0]), "r"(a[1]), "r"(a[2]), "r"(a[3]),
          "r"(b[0]), "r"(b[1]));
}
__device__ __forceinline__ uint32_t f2h2(float lo, float hi) {
    __half2 p = __floats2half2_rn(lo, hi);
    return *reinterpret_cast<uint32_t*>(&p);
}
__device__ __forceinline__ uint32_t addrelu(uint32_t a, uint32_t b) {
    __half2 s = __hmax2(__hadd2(*reinterpret_cast<__half2*>(&a),
                                *reinterpret_cast<__half2*>(&b)),
                        __float2half2_rn(0.f));
    return *reinterpret_cast<uint32_t*>(&s);
}
__device__ __forceinline__ void cp16(uint32_t s, const void* g) {
    asm volatile("cp.async.cg.shared.global [%0], [%1], 16;\n" :: "r"(s), "l"(g));
}
__device__ __forceinline__ void cp_commit() {
    asm volatile("cp.async.commit_group;\n");
}
template <int N>
__device__ __forceinline__ void cp_wait() {
    asm volatile("cp.async.wait_group %0;\n" :: "n"(N));
}
__device__ __forceinline__ uint32_t smem_u32(const void* p) {
    uint32_t a;
    asm("{ .reg .u64 t; cvta.to.shared.u64 t, %1; cvt.u32.u64 %0, t; }" : "=r"(a) : "l"(p));
    return a;
}

// ============================================================================
// Kernel 0: prep — W1 -> g_W1T fp16 [1024][128]; W2 -> g_W2T fp16 [128][512]
// ============================================================================
__global__ __launch_bounds__(256) void prep_kernel(
    const float* __restrict__ W1, const float* __restrict__ W2)
{
    int bid = blockIdx.x;
    int tid = threadIdx.x;
    if (bid < 512) {
        int idx = bid * 256 + tid;
        int k = idx >> 10;
        int n = idx & 1023;
        float v = (n < 512) ? W1[(size_t)k * 512 + n]
                            : W1[(size_t)(128 + k) * 512 + (n - 512)];
        g_W1T[(size_t)n * 128 + k] = __float2half_rn(v);
    } else {
        int idx = (bid - 512) * 256 + tid;
        int k = idx >> 7;
        int n = idx & 127;
        g_W2T[(size_t)n * 512 + k] = __float2half_rn(W2[(size_t)k * 128 + n]);
    }
}

// ============================================================================
// Kernel 1: P = emb @ Wcat (+ b1 on cols<512) -> fp16.
// grid 782: each CTA owns 128 rows, loops the 8 n-blocks internally.
// emb staged ONCE (A tile); W1T B-tile reloaded per nblk (L2-hot).
// ============================================================================
#define PC_STR 68
#define PC_SMEM (2 * 128 * PC_STR * 4)

__global__ __launch_bounds__(256, 2) void precompute_kernel(
    const float* __restrict__ emb, const float* __restrict__ b1)
{
    extern __shared__ char smem_raw[];
    uint32_t* As = (uint32_t*)smem_raw;
    uint32_t* Ws = As + 128 * PC_STR;

    const int tid  = threadIdx.x;
    const int warp = tid >> 5;
    const int lane = tid & 31;
    const int q    = lane & 3;
    const int lr   = lane >> 2;
    const int wm   = warp >> 2;
    const int wn   = warp & 3;
    const int row0 = blockIdx.x * 128;

    const int rj = tid & 15;
    const int rr = tid >> 4;

    // ---- stage A tile once: emb rows -> fp16 ----
    #pragma unroll
    for (int pass = 0; pass < 8; pass++) {
        int r = pass * 16 + rr;
        int node = row0 + r;
        if (node >= NN) node = NN - 1;
        const float4* src = (const float4*)(emb + (size_t)node * HDIM + rj * 8);
        float4 a0 = src[0];
        float4 a1 = src[1];
        uint4 h;
        h.x = f2h2(a0.x, a0.y);
        h.y = f2h2(a0.z, a0.w);
        h.z = f2h2(a1.x, a1.y);
        h.w = f2h2(a1.z, a1.w);
        *(uint4*)(As + r * PC_STR + rj * 4) = h;
    }

    #pragma unroll 1
    for (int nblk = 0; nblk < 8; nblk++) {
        // stage B tile for this nblk (32 KB, L2-hot after wave 1)
        __syncthreads();   // prior mma reads of Ws done (and A ready on iter 0)
        #pragma unroll
        for (int pass = 0; pass < 8; pass++) {
            int r = pass * 16 + rr;
            uint4 v = *(const uint4*)(g_W1T + (size_t)(nblk * 128 + r) * 128 + rj * 8);
            *(uint4*)(Ws + r * PC_STR + rj * 4) = v;
        }
        __syncthreads();

        float acc[4][4][4];
        #pragma unroll
        for (int mt = 0; mt < 4; mt++)
            #pragma unroll
            for (int nt = 0; nt < 4; nt++)
                #pragma unroll
                for (int i = 0; i < 4; i++) acc[mt][nt][i] = 0.f;

        #pragma unroll
        for (int s = 0; s < 8; s++) {
            uint32_t bfr[4][2];
            #pragma unroll
            for (int nt = 0; nt < 4; nt++) {
                const uint32_t* bp = Ws + (wn * 32 + nt * 8 + lr) * PC_STR + q + 8 * s;
                bfr[nt][0] = bp[0];
                bfr[nt][1] = bp[4];
            }
            #pragma unroll
            for (int mt = 0; mt < 4; mt++) {
                const uint32_t* ap = As + (wm * 64 + mt * 16 + lr) * PC_STR + q + 8 * s;
                uint32_t a[4];
                a[0] = ap[0];
                a[1] = ap[8 * PC_STR];
                a[2] = ap[4];
                a[3] = ap[8 * PC_STR + 4];
                #pragma unroll
                for (int nt = 0; nt < 4; nt++)
                    mma_f16(acc[mt][nt], a, bfr[nt]);
            }
        }

        const bool bias = (nblk < 4);
        #pragma unroll
        for (int mt = 0; mt < 4; mt++) {
            int n0 = row0 + wm * 64 + mt * 16 + lr;
            #pragma unroll
            for (int nt = 0; nt < 4; nt++) {
                int c = nblk * 128 + wn * 32 + nt * 8 + q * 2;
                float a0 = acc[mt][nt][0], a1 = acc[mt][nt][1];
                float a2 = acc[mt][nt][2], a3 = acc[mt][nt][3];
                if (bias) {
                    float u = b1[c], v = b1[c + 1];
                    a0 += u; a1 += v; a2 += u; a3 += v;
                }
                if (n0 < NN)
                    *(uint32_t*)(g_Ph + (size_t)n0 * 1024 + c) = f2h2(a0, a1);
                if (n0 + 8 < NN)
                    *(uint32_t*)(g_Ph + (size_t)(n0 + 8) * 1024 + c) = f2h2(a2, a3);
            }
        }
    }
}

// ============================================================================
// Kernel 2: edge MLP — VERBATIM R6 609us kernel. 128 threads (4 warps,
// 2M x 2N), tile 128 e x 128 N, K=512 in 8 chunks of 64. LDG->reg gather
// pipelined 2 chunks ahead; h1=relu(Pa+Pb) fused into the single STS;
// W2 via cp.async; 1 syncthreads per chunk. f32 accumulators.
// ============================================================================
#define HS_STR 36                         // uint32 words per 64-half row
#define H1_B   (128 * HS_STR * 4)         // 18432 bytes per h1 buffer
#define STG_B  (2 * H1_B)                 // h1 | W2 per stage = 36864
#define EK_SMEM (2 * STG_B + 3072)        // 76800

__global__ __launch_bounds__(128, 2) void edge_kernel(
    const int* __restrict__ ei,
    const float* __restrict__ b2, const float* __restrict__ W3,
    const float* __restrict__ b3, float* __restrict__ out)
{
    extern __shared__ char smem_raw[];
    uint32_t* pipe = (uint32_t*)smem_raw;                    // [2][h1|W2]
    float* b2s  = (float*)(smem_raw + 2 * STG_B);            // 128
    float* w3s  = (float*)(smem_raw + 2 * STG_B + 512);      // 128
    int*   colS = (int*)  (smem_raw + 2 * STG_B + 1024);     // 128
    int*   rowS = (int*)  (smem_raw + 2 * STG_B + 1536);     // 128
    float* partS = (float*)(smem_raw + 2 * STG_B + 2048);    // 256

    const int tid  = threadIdx.x;
    const int warp = tid >> 5;
    const int lane = tid & 31;
    const int q    = lane & 3;
    const int lr   = lane >> 2;
    const int wy   = warp >> 1;
    const int wx   = warp & 1;
    const int e0   = blockIdx.x * 128;

    {
        int eg = e0 + tid;
        int c = 0, r = 0;
        if (eg < E_TOTAL) { c = ei[eg]; r = ei[E_TOTAL + eg]; }
        colS[tid] = c; rowS[tid] = r;
        b2s[tid] = b2[tid];
        w3s[tid] = W3[tid];
    }
    __syncthreads();

    const uint32_t smemBase = smem_u32(pipe);

    // ---- gather plan: 4 threads/edge (j4 = 16B col), 4 passes of 32 edges ----
    const int j4 = tid & 3;
    const int eT = tid >> 2;              // 0..31
    uint32_t paOff[4], pbOff[4], hD[4];
    #pragma unroll
    for (int p = 0; p < 4; p++) {
        int e = p * 32 + eT;
        paOff[p] = (uint32_t)colS[e] * 2048u + j4 * 16u;
        pbOff[p] = (uint32_t)rowS[e] * 2048u + 1024u + j4 * 16u;
        hD[p]    = smemBase + (uint32_t)(e * HS_STR + j4 * 4) * 4u;
    }
    // ---- W2 staging plan: 8 threads/row (j8 = 16B col), 8 passes of 16 rows ----
    const int j8  = tid & 7;
    const int n16 = tid >> 3;             // 0..15
    uint32_t wOff[8], wD[8];
    #pragma unroll
    for (int p = 0; p < 8; p++) {
        int n = p * 16 + n16;
        wOff[p] = (uint32_t)n * 1024u + j8 * 16u;
        wD[p]   = smemBase + (uint32_t)H1_B + (uint32_t)(n * HS_STR + j8 * 4) * 4u;
    }
    const char* gP = (const char*)g_Ph;
    const char* gW = (const char*)g_W2T;

    uint4 rA[4][2], rB[4][2];             // P gather regs (one chunk in flight)

    // ---- prologue ----
    #pragma unroll
    for (int p = 0; p < 4; p++) {
        rA[p][0] = *(const uint4*)(gP + paOff[p]);
        rA[p][1] = *(const uint4*)(gP + paOff[p] + 64);
        rB[p][0] = *(const uint4*)(gP + pbOff[p]);
        rB[p][1] = *(const uint4*)(gP + pbOff[p] + 64);
    }
    #pragma unroll
    for (int p = 0; p < 8; p++) cp16(wD[p], gW + wOff[p]);
    cp_commit();
    #pragma unroll
    for (int p = 0; p < 4; p++)
        #pragma unroll
        for (int h = 0; h < 2; h++) {
            uint4 v;
            v.x = addrelu(rA[p][h].x, rB[p][h].x);
            v.y = addrelu(rA[p][h].y, rB[p][h].y);
            v.z = addrelu(rA[p][h].z, rB[p][h].z);
            v.w = addrelu(rA[p][h].w, rB[p][h].w);
            asm volatile("st.shared.v4.b32 [%0], {%1,%2,%3,%4};"
                         :: "r"(hD[p] + h * 64u), "r"(v.x), "r"(v.y), "r"(v.z), "r"(v.w)
                         : "memory");
        }
    #pragma unroll
    for (int p = 0; p < 4; p++) {
        rA[p][0] = *(const uint4*)(gP + paOff[p] + 128);
        rA[p][1] = *(const uint4*)(gP + paOff[p] + 192);
        rB[p][0] = *(const uint4*)(gP + pbOff[p] + 128);
        rB[p][1] = *(const uint4*)(gP + pbOff[p] + 192);
    }
    cp_wait<0>();
    __syncthreads();

    float acc[4][8][4];
    #pragma unroll
    for (int mt = 0; mt < 4; mt++)
        #pragma unroll
        for (int nt = 0; nt < 8; nt++)
            #pragma unroll
            for (int i = 0; i < 4; i++) acc[mt][nt][i] = 0.f;

    #pragma unroll 1
    for (int kc = 0; kc < 8; kc++) {
        const uint32_t curB = (uint32_t)(kc & 1) * STG_B;
        if (kc < 7) {
            const uint32_t nb = (uint32_t)((kc + 1) & 1) * STG_B;
            // STS h1(kc+1) from regs
            #pragma unroll
            for (int p = 0; p < 4; p++)
                #pragma unroll
                for (int h = 0; h < 2; h++) {
                    uint4 v;
                    v.x = addrelu(rA[p][h].x, rB[p][h].x);
                    v.y = addrelu(rA[p][h].y, rB[p][h].y);
                    v.z = addrelu(rA[p][h].z, rB[p][h].z);
                    v.w = addrelu(rA[p][h].w, rB[p][h].w);
                    asm volatile("st.shared.v4.b32 [%0], {%1,%2,%3,%4};"
                                 :: "r"(hD[p] + nb + h * 64u),
                                    "r"(v.x), "r"(v.y), "r"(v.z), "r"(v.w) : "memory");
                }
            // cp W2(kc+1)
            {
                const uint32_t kb = (uint32_t)(kc + 1) * 128u;
                #pragma unroll
                for (int p = 0; p < 8; p++) cp16(wD[p] + nb, gW + wOff[p] + kb);
                cp_commit();
            }
            // LDG P(kc+2) -> regs
            if (kc < 6) {
                const uint32_t kb = (uint32_t)(kc + 2) * 128u;
                #pragma unroll
                for (int p = 0; p < 4; p++) {
                    rA[p][0] = *(const uint4*)(gP + paOff[p] + kb);
                    rA[p][1] = *(const uint4*)(gP + paOff[p] + kb + 64);
                    rB[p][0] = *(const uint4*)(gP + pbOff[p] + kb);
                    rB[p][1] = *(const uint4*)(gP + pbOff[p] + kb + 64);
                }
            }
        }
        // mma(kc)
        const uint32_t* Hs = pipe + (curB >> 2);
        const uint32_t* Ws = Hs + (H1_B >> 2);
        #pragma unroll
        for (int s = 0; s < 4; s++) {
            uint32_t bfr[8][2];
            #pragma unroll
            for (int nt = 0; nt < 8; nt++) {
                const uint32_t* bp = Ws + (wx * 64 + nt * 8 + lr) * HS_STR + q + 8 * s;
                bfr[nt][0] = bp[0];
                bfr[nt][1] = bp[4];
            }
            #pragma unroll
            for (int mt = 0; mt < 4; mt++) {
                int ro = (wy * 64 + mt * 16 + lr) * HS_STR + q + 8 * s;
                uint32_t a[4];
                a[0] = Hs[ro];
                a[1] = Hs[ro + 8 * HS_STR];
                a[2] = Hs[ro + 4];
                a[3] = Hs[ro + 8 * HS_STR + 4];
                #pragma unroll
                for (int nt = 0; nt < 8; nt++)
                    mma_f16(acc[mt][nt], a, bfr[nt]);
            }
        }
        if (kc < 7) {
            cp_wait<0>();
            __syncthreads();
        }
    }
    __syncthreads();

    // ---- epilogue ----
    #pragma unroll
    for (int mt = 0; mt < 4; mt++) {
        float p0 = 0.f, p1 = 0.f;
        #pragma unroll
        for (int nt = 0; nt < 8; nt++) {
            int n = wx * 64 + nt * 8 + q * 2;
            float w0 = w3s[n], w1 = w3s[n + 1];
            float g0 = b2s[n], g1 = b2s[n + 1];
            p0 += fmaxf(acc[mt][nt][0] + g0, 0.f) * w0 + fmaxf(acc[mt][nt][1] + g1, 0.f) * w1;
            p1 += fmaxf(acc[mt][nt][2] + g0, 0.f) * w0 + fmaxf(acc[mt][nt][3] + g1, 0.f) * w1;
        }
        p0 += __shfl_xor_sync(0xffffffffu, p0, 1);
        p0 += __shfl_xor_sync(0xffffffffu, p0, 2);
        p1 += __shfl_xor_sync(0xffffffffu, p1, 1);
        p1 += __shfl_xor_sync(0xffffffffu, p1, 2);
        if (q == 0) {
            int rl = wy * 64 + mt * 16 + lr;
            partS[wx * 128 + rl]     = p0;
            partS[wx * 128 + rl + 8] = p1;
        }
    }
    __syncthreads();
    {
        float s = partS[tid] + partS[128 + tid] + b3[0];
        int eg = e0 + tid;
        if (eg < E_TOTAL) out[eg] = 1.f / (1.f + expf(-s));
    }
}

// ============================================================================
extern "C" void kernel_launch(void* const* d_in, const int* in_sizes, int n_in,
                              void* d_out, int out_size)
{
    const float* emb = (const float*)d_in[0];
    const int*   ei  = (const int*)d_in[1];
    const float* W1  = (const float*)d_in[2];
    const float* b1  = (const float*)d_in[3];
    const float* W2  = (const float*)d_in[4];
    const float* b2  = (const float*)d_in[5];
    const float* W3  = (const float*)d_in[6];
    const float* b3  = (const float*)d_in[7];
    float* out = (float*)d_out;

    cudaFuncSetAttribute(precompute_kernel,
                         cudaFuncAttributeMaxDynamicSharedMemorySize, PC_SMEM);
    cudaFuncSetAttribute(edge_kernel,
                         cudaFuncAttributeMaxDynamicSharedMemorySize, EK_SMEM);

    prep_kernel<<<768, 256>>>(W1, W2);
    precompute_kernel<<<782, 256, PC_SMEM>>>(emb, b1);
    edge_kernel<<<7813, 128, EK_SMEM>>>(ei, b2, W3, b3, out);
}